// round 4
// baseline (speedup 1.0000x reference)
#include <cuda_runtime.h>
#include <cuda_fp16.h>
#include <cstdint>
#include <cstddef>

// ---------------------------------------------------------------------------
// Problem constants
// ---------------------------------------------------------------------------
static constexpr int IN_DIM  = 4096;     // K
static constexpr int OUT_DIM = 32768;    // N
static constexpr int BATCH   = 4096;     // M
static constexpr float WSCALE = 8192.0f; // 2^13: lift W out of fp16 subnormals
static constexpr float EPSV   = 1e-8f;

// GEMM tiling (Ampere-style mma.sync path; tcgen05 is not reachable from the
// harness's compute_103 PTX target)
static constexpr int BM = 128;
static constexpr int BN = 128;
static constexpr int BK = 32;                     // halfs per stage
static constexpr int NSTAGES = 4;
static constexpr int KITERS = IN_DIM / BK;        // 128
static constexpr int ROWB   = 80;                 // 64B data + 16B pad per row
static constexpr int ASTAGE = BM * ROWB;          // 10240 B
static constexpr int BSTAGE = BN * ROWB;          // 10240 B
static constexpr int STAGE  = ASTAGE + BSTAGE;    // 20480 B
static constexpr int SMEM_TOTAL = NSTAGES * STAGE; // 81920 B

// ---------------------------------------------------------------------------
// Device-global scratch (allocation-free rule)
// ---------------------------------------------------------------------------
__device__ __half g_x16[(size_t)BATCH * IN_DIM];      // 32 MB
__device__ __half g_w16t[(size_t)OUT_DIM * IN_DIM];   // 256 MB: W^T * WSCALE
__device__ float  g_inv_xn[BATCH];
__device__ float  g_inv_wn[OUT_DIM];

// ---------------------------------------------------------------------------
// PTX helpers
// ---------------------------------------------------------------------------
__device__ __forceinline__ uint32_t smem_u32(const void* p) {
    return (uint32_t)__cvta_generic_to_shared(p);
}

#define CP_ASYNC16(dst, src) \
    asm volatile("cp.async.cg.shared.global [%0], [%1], 16;" :: "r"(dst), "l"(src) : "memory")
#define CP_COMMIT()  asm volatile("cp.async.commit_group;" ::: "memory")
#define CP_WAIT2()   asm volatile("cp.async.wait_group 2;" ::: "memory")

__device__ __forceinline__ void ldsm_x4(uint32_t* r, uint32_t addr) {
    asm volatile("ldmatrix.sync.aligned.m8n8.x4.shared.b16 {%0,%1,%2,%3}, [%4];"
                 : "=r"(r[0]), "=r"(r[1]), "=r"(r[2]), "=r"(r[3])
                 : "r"(addr));
}

__device__ __forceinline__ void mma16816(float* c, const uint32_t* a, const uint32_t* b) {
    asm volatile(
        "mma.sync.aligned.m16n8k16.row.col.f32.f16.f16.f32 "
        "{%0,%1,%2,%3}, {%4,%5,%6,%7}, {%8,%9}, {%0,%1,%2,%3};"
        : "+f"(c[0]), "+f"(c[1]), "+f"(c[2]), "+f"(c[3])
        : "r"(a[0]), "r"(a[1]), "r"(a[2]), "r"(a[3]), "r"(b[0]), "r"(b[1]));
}

// ---------------------------------------------------------------------------
// Kernel 1: x (f32) -> g_x16 (fp16) + row inverse norms. One block per row.
// ---------------------------------------------------------------------------
__global__ __launch_bounds__(256) void k_prep_x(const float* __restrict__ x) {
    __shared__ float red[8];
    int b = blockIdx.x;
    int t = threadIdx.x;
    const float4* xr = (const float4*)(x + (size_t)b * IN_DIM);
    __half2* dst = (__half2*)(g_x16 + (size_t)b * IN_DIM);
    float s = 0.0f;
#pragma unroll
    for (int i = 0; i < 4; i++) {
        int e4 = t + 256 * i;
        float4 v = xr[e4];
        s += v.x * v.x + v.y * v.y + v.z * v.z + v.w * v.w;
        dst[e4 * 2 + 0] = __floats2half2_rn(v.x, v.y);
        dst[e4 * 2 + 1] = __floats2half2_rn(v.z, v.w);
    }
#pragma unroll
    for (int o = 16; o > 0; o >>= 1) s += __shfl_down_sync(0xffffffffu, s, o);
    if ((t & 31) == 0) red[t >> 5] = s;
    __syncthreads();
    if (t == 0) {
        float tot = 0.0f;
#pragma unroll
        for (int w = 0; w < 8; w++) tot += red[w];
        g_inv_xn[b] = 1.0f / fmaxf(sqrtf(tot), EPSV);
    }
}

// ---------------------------------------------------------------------------
// Kernel 2: transpose + scale: W[k][o] (f32) -> g_w16t[o][k] (fp16 * WSCALE)
// ---------------------------------------------------------------------------
__global__ __launch_bounds__(256) void k_transpose_w(const float* __restrict__ w) {
    __shared__ float tile[32][33];
    int o0 = blockIdx.x * 32;
    int k0 = blockIdx.y * 32;
    int t = threadIdx.x;
#pragma unroll
    for (int i = 0; i < 4; i++) {
        int idx = t + 256 * i;
        int r = idx >> 5;                 // k within tile
        int c = idx & 31;                 // o within tile
        tile[r][c] = w[(size_t)(k0 + r) * OUT_DIM + o0 + c];
    }
    __syncthreads();
#pragma unroll
    for (int i = 0; i < 4; i++) {
        int idx = t + 256 * i;
        int ro = idx >> 5;                // o within tile
        int ck = idx & 31;                // k within tile
        g_w16t[(size_t)(o0 + ro) * IN_DIM + k0 + ck] =
            __float2half_rn(tile[ck][ro] * WSCALE);
    }
}

// ---------------------------------------------------------------------------
// Kernel 3: column inverse norms from scaled fp16 W^T (coalesced K-major)
// ---------------------------------------------------------------------------
__global__ __launch_bounds__(256) void k_wnorm() {
    int warp = threadIdx.x >> 5;
    int lane = threadIdx.x & 31;
    int o = blockIdx.x * 8 + warp;
    const __half2* row = (const __half2*)(g_w16t + (size_t)o * IN_DIM);
    float s = 0.0f;
#pragma unroll 8
    for (int i = lane; i < IN_DIM / 2; i += 32) {
        float2 v = __half22float2(row[i]);
        s += v.x * v.x + v.y * v.y;
    }
#pragma unroll
    for (int off = 16; off > 0; off >>= 1) s += __shfl_down_sync(0xffffffffu, s, off);
    if (lane == 0) g_inv_wn[o] = 1.0f / fmaxf(sqrtf(s), WSCALE * EPSV);
}

// ---------------------------------------------------------------------------
// Kernel 4: pipelined HMMA GEMM (128x128x32, 4 stages) + cosine epilogue
// 256 threads = 8 warps (2 along M x 4 along N), warp tile 64x32
// ---------------------------------------------------------------------------
__global__ __launch_bounds__(256, 2) void k_gemm(float* __restrict__ out) {
    extern __shared__ __align__(128) char smem[];
    const uint32_t sbase = smem_u32(smem);
    const int tid  = threadIdx.x;
    const int wid  = tid >> 5;
    const int lane = tid & 31;

    // N-major raster: consecutive CTAs share B tiles; all X stays L2-resident
    const int mt = blockIdx.x & 31;
    const int nt = blockIdx.x >> 5;
    const int m0 = mt * BM;
    const int n0 = nt * BN;

    const int wm = wid & 1;        // 0..1 -> 64 rows each
    const int wn = wid >> 1;       // 0..3 -> 32 cols each
    const int m_w = wm * 64;
    const int n_w = wn * 32;

    // ---- producer addressing: each thread owns 2 A-chunks + 2 B-chunks ----
    const int ar = tid >> 2;       // row 0..63 (second chunk: +64)
    const int aj = tid & 3;        // 16B chunk within row
    const __half* srcA0 = g_x16  + (size_t)(m0 + ar) * IN_DIM + aj * 8;
    const __half* srcB0 = g_w16t + (size_t)(n0 + ar) * IN_DIM + aj * 8;
    const size_t half64rows = (size_t)64 * IN_DIM;
    const uint32_t dA0 = sbase + (uint32_t)(ar * ROWB + aj * 16);
    const uint32_t dA1 = dA0 + 64 * ROWB;
    const uint32_t dB0 = dA0 + ASTAGE;
    const uint32_t dB1 = dB0 + 64 * ROWB;

#define LOAD_STAGE(slot, kk) do {                                          \
        const uint32_t so = (uint32_t)(slot) * STAGE;                      \
        const int koff = (kk) * BK;                                        \
        CP_ASYNC16(dA0 + so, (const void*)(srcA0 + koff));                 \
        CP_ASYNC16(dA1 + so, (const void*)(srcA0 + half64rows + koff));    \
        CP_ASYNC16(dB0 + so, (const void*)(srcB0 + koff));                 \
        CP_ASYNC16(dB1 + so, (const void*)(srcB0 + half64rows + koff));    \
    } while (0)

    LOAD_STAGE(0, 0); CP_COMMIT();
    LOAD_STAGE(1, 1); CP_COMMIT();
    LOAD_STAGE(2, 2); CP_COMMIT();

    // ---- ldmatrix lane offsets ----
    // A x4: matrix i = lane>>3; row = m_w + mt16*16 + (i&1)*8 + lane%8;
    //       kchunk sel = i>>1  -> byte sel*16 (+ s*32 per k-step)
    const uint32_t a_off =
        (uint32_t)((m_w + ((lane >> 3) & 1) * 8 + (lane & 7)) * ROWB
                   + (lane >> 4) * 16);
    // B x4 (two n8-tiles per load): matrix i = lane>>3;
    //       n row = n_w + (i>>1)*8 + lane%8; kchunk sel = i&1
    const uint32_t b_off =
        (uint32_t)((n_w + (lane >> 4) * 8 + (lane & 7)) * ROWB
                   + ((lane >> 3) & 1) * 16) + (uint32_t)ASTAGE;

    float acc[4][4][4];
#pragma unroll
    for (int i = 0; i < 4; i++)
#pragma unroll
        for (int j = 0; j < 4; j++)
#pragma unroll
            for (int e = 0; e < 4; e++) acc[i][j][e] = 0.0f;

    for (int ki = 0; ki < KITERS; ki++) {
        CP_WAIT2();
        __syncthreads();
        if (ki + 3 < KITERS) LOAD_STAGE((ki + 3) & 3, ki + 3);
        CP_COMMIT();

        const uint32_t st = sbase + (uint32_t)(ki & 3) * STAGE;
#pragma unroll
        for (int s = 0; s < 2; s++) {                 // two k16 steps per stage
            uint32_t afr[4][4];
#pragma unroll
            for (int mi = 0; mi < 4; mi++)
                ldsm_x4(afr[mi], st + a_off + (uint32_t)(mi * 16 * ROWB + s * 32));
            uint32_t bfr[4][2];
#pragma unroll
            for (int p = 0; p < 2; p++) {
                uint32_t r[4];
                ldsm_x4(r, st + b_off + (uint32_t)(p * 16 * ROWB + s * 32));
                bfr[2 * p][0] = r[0]; bfr[2 * p][1] = r[1];
                bfr[2 * p + 1][0] = r[2]; bfr[2 * p + 1][1] = r[3];
            }
#pragma unroll
            for (int mi = 0; mi < 4; mi++)
#pragma unroll
                for (int ni = 0; ni < 4; ni++)
                    mma16816(acc[mi][ni], afr[mi], bfr[ni]);
        }
    }

    // ---- epilogue: cosine scaling, direct float2 stores ----
    const int g = lane >> 2;
    const int q = lane & 3;
#pragma unroll
    for (int mi = 0; mi < 4; mi++) {
        const int r0 = m0 + m_w + mi * 16 + g;
        const float sx0 = g_inv_xn[r0];
        const float sx1 = g_inv_xn[r0 + 8];
#pragma unroll
        for (int ni = 0; ni < 4; ni++) {
            const int c = n0 + n_w + ni * 8 + q * 2;
            const float w0 = g_inv_wn[c];
            const float w1 = g_inv_wn[c + 1];
            float2 v0 = make_float2(acc[mi][ni][0] * sx0 * w0,
                                    acc[mi][ni][1] * sx0 * w1);
            float2 v1 = make_float2(acc[mi][ni][2] * sx1 * w0,
                                    acc[mi][ni][3] * sx1 * w1);
            *(float2*)&out[(size_t)r0 * OUT_DIM + c] = v0;
            *(float2*)&out[(size_t)(r0 + 8) * OUT_DIM + c] = v1;
        }
    }
#undef LOAD_STAGE
}

// ---------------------------------------------------------------------------
// Launch
// ---------------------------------------------------------------------------
extern "C" void kernel_launch(void* const* d_in, const int* in_sizes, int n_in,
                              void* d_out, int out_size) {
    const float* x = (const float*)d_in[0];       // (4096, 4096)
    const float* w = (const float*)d_in[1];       // (4096, 32768)
    float* out = (float*)d_out;                   // (4096, 32768)

    cudaFuncSetAttribute(k_gemm, cudaFuncAttributeMaxDynamicSharedMemorySize,
                         SMEM_TOTAL);

    k_prep_x<<<BATCH, 256>>>(x);
    k_transpose_w<<<dim3(OUT_DIM / 32, IN_DIM / 32), 256>>>(w);
    k_wnorm<<<OUT_DIM / 8, 256>>>();
    k_gemm<<<(BATCH / BM) * (OUT_DIM / BN), 256, SMEM_TOTAL>>>(out);
}

// round 7
// speedup vs baseline: 1.1767x; 1.1767x over previous
#include <cuda_runtime.h>
#include <cuda_fp16.h>
#include <cstdint>
#include <cstddef>

// ---------------------------------------------------------------------------
// Problem constants
// ---------------------------------------------------------------------------
static constexpr int IN_DIM  = 4096;     // K
static constexpr int OUT_DIM = 32768;    // N
static constexpr int BATCH   = 4096;     // M
static constexpr float WSCALE = 8192.0f; // 2^13: lift W out of fp16 subnormals
static constexpr float EPSV   = 1e-8f;

// GEMM tiling: 128x128 CTA, BK=64 per stage, 3-stage cp.async ring,
// 4 warps (128 thr), warp tile 64x64.  (tcgen05 unreachable: harness builds
// through compute_103 virtual PTX which rejects sm_103a features.)
static constexpr int BM = 128;
static constexpr int BN = 128;
static constexpr int BK = 64;                      // halfs per stage = 128B/row
static constexpr int NSTAGES = 3;
static constexpr int KITERS = IN_DIM / BK;         // 64
static constexpr int ASTAGE = BM * 128;            // 16 KB
static constexpr int BSTAGE = BN * 128;            // 16 KB
static constexpr int STAGE  = ASTAGE + BSTAGE;     // 32 KB
static constexpr int SMEM_TOTAL = NSTAGES * STAGE; // 96 KB  (x2 CTAs = 192KB)

// ---------------------------------------------------------------------------
// Device-global scratch (allocation-free rule)
// ---------------------------------------------------------------------------
__device__ __align__(256) __half g_x16[(size_t)BATCH * IN_DIM];     // 32 MB
__device__ __align__(256) __half g_w16t[(size_t)OUT_DIM * IN_DIM];  // 256 MB
__device__ float  g_inv_xn[BATCH];
__device__ float  g_inv_wn[OUT_DIM];

// ---------------------------------------------------------------------------
// PTX helpers
// ---------------------------------------------------------------------------
__device__ __forceinline__ uint32_t smem_u32(const void* p) {
    return (uint32_t)__cvta_generic_to_shared(p);
}

#define CP_ASYNC16(dst, src) \
    asm volatile("cp.async.cg.shared.global [%0], [%1], 16;" :: "r"(dst), "l"(src) : "memory")
#define CP_COMMIT()  asm volatile("cp.async.commit_group;" ::: "memory")
#define CP_WAIT1()   asm volatile("cp.async.wait_group 1;" ::: "memory")

__device__ __forceinline__ void ldsm_x4(uint32_t* r, uint32_t addr) {
    asm volatile("ldmatrix.sync.aligned.m8n8.x4.shared.b16 {%0,%1,%2,%3}, [%4];"
                 : "=r"(r[0]), "=r"(r[1]), "=r"(r[2]), "=r"(r[3])
                 : "r"(addr));
}

__device__ __forceinline__ void mma16816(float* c, const uint32_t* a, const uint32_t* b) {
    asm volatile(
        "mma.sync.aligned.m16n8k16.row.col.f32.f16.f16.f32 "
        "{%0,%1,%2,%3}, {%4,%5,%6,%7}, {%8,%9}, {%0,%1,%2,%3};"
        : "+f"(c[0]), "+f"(c[1]), "+f"(c[2]), "+f"(c[3])
        : "r"(a[0]), "r"(a[1]), "r"(a[2]), "r"(a[3]), "r"(b[0]), "r"(b[1]));
}

// ---------------------------------------------------------------------------
// Kernel 1: x (f32) -> g_x16 (fp16) + row inverse norms. One block per row.
// ---------------------------------------------------------------------------
__global__ __launch_bounds__(256) void k_prep_x(const float* __restrict__ x) {
    __shared__ float red[8];
    int b = blockIdx.x;
    int t = threadIdx.x;
    const float4* xr = (const float4*)(x + (size_t)b * IN_DIM);
    __half2* dst = (__half2*)(g_x16 + (size_t)b * IN_DIM);
    float s = 0.0f;
#pragma unroll
    for (int i = 0; i < 4; i++) {
        int e4 = t + 256 * i;
        float4 v = xr[e4];
        s += v.x * v.x + v.y * v.y + v.z * v.z + v.w * v.w;
        dst[e4 * 2 + 0] = __floats2half2_rn(v.x, v.y);
        dst[e4 * 2 + 1] = __floats2half2_rn(v.z, v.w);
    }
#pragma unroll
    for (int o = 16; o > 0; o >>= 1) s += __shfl_down_sync(0xffffffffu, s, o);
    if ((t & 31) == 0) red[t >> 5] = s;
    __syncthreads();
    if (t == 0) {
        float tot = 0.0f;
#pragma unroll
        for (int w = 0; w < 8; w++) tot += red[w];
        g_inv_xn[b] = 1.0f / fmaxf(sqrtf(tot), EPSV);
    }
}

// ---------------------------------------------------------------------------
// Kernel 2: transpose + scale: W[k][o] (f32) -> g_w16t[o][k] (fp16 * WSCALE)
// ---------------------------------------------------------------------------
__global__ __launch_bounds__(256) void k_transpose_w(const float* __restrict__ w) {
    __shared__ float tile[32][33];
    int o0 = blockIdx.x * 32;
    int k0 = blockIdx.y * 32;
    int t = threadIdx.x;
#pragma unroll
    for (int i = 0; i < 4; i++) {
        int idx = t + 256 * i;
        int r = idx >> 5;                 // k within tile
        int c = idx & 31;                 // o within tile
        tile[r][c] = w[(size_t)(k0 + r) * OUT_DIM + o0 + c];
    }
    __syncthreads();
#pragma unroll
    for (int i = 0; i < 4; i++) {
        int idx = t + 256 * i;
        int ro = idx >> 5;                // o within tile
        int ck = idx & 31;                // k within tile
        g_w16t[(size_t)(o0 + ro) * IN_DIM + k0 + ck] =
            __float2half_rn(tile[ck][ro] * WSCALE);
    }
}

// ---------------------------------------------------------------------------
// Kernel 3: column inverse norms from scaled fp16 W^T (coalesced K-major)
// ---------------------------------------------------------------------------
__global__ __launch_bounds__(256) void k_wnorm() {
    int warp = threadIdx.x >> 5;
    int lane = threadIdx.x & 31;
    int o = blockIdx.x * 8 + warp;
    const __half2* row = (const __half2*)(g_w16t + (size_t)o * IN_DIM);
    float s = 0.0f;
#pragma unroll 8
    for (int i = lane; i < IN_DIM / 2; i += 32) {
        float2 v = __half22float2(row[i]);
        s += v.x * v.x + v.y * v.y;
    }
#pragma unroll
    for (int off = 16; off > 0; off >>= 1) s += __shfl_down_sync(0xffffffffu, s, off);
    if (lane == 0) g_inv_wn[o] = 1.0f / fmaxf(sqrtf(s), WSCALE * EPSV);
}

// ---------------------------------------------------------------------------
// Kernel 4: pipelined HMMA GEMM (128x128x64, 3 stages, swizzled 128B rows)
// 128 threads = 4 warps (2 along M x 2 along N), warp tile 64x64
// ---------------------------------------------------------------------------
__global__ __launch_bounds__(128, 2) void k_gemm(float* __restrict__ out) {
    extern __shared__ __align__(128) char smem[];
    const uint32_t sbase = smem_u32(smem);
    const int tid  = threadIdx.x;
    const int wid  = tid >> 5;
    const int lane = tid & 31;

    // N-major raster: consecutive CTAs share B; all of X stays L2-resident
    const int mt = blockIdx.x & 31;
    const int nt = blockIdx.x >> 5;
    const int m0 = mt * BM;
    const int n0 = nt * BN;

    const int m_w = (wid & 1) * 64;
    const int n_w = (wid >> 1) * 64;

    // ---- producer addressing: 16 x 16B cp.async per thread per stage ----
    // thread -> (r0 = tid>>3 in [0,16), j = tid&7); rows r0 + 16*i, i in [0,8)
    const int r0 = tid >> 3;
    const int j  = tid & 7;
    const uint32_t swj = (uint32_t)((j ^ (r0 & 7)) * 16);   // swizzled chunk
    const __half* srcA = g_x16  + (size_t)(m0 + r0) * IN_DIM + j * 8;
    const __half* srcB = g_w16t + (size_t)(n0 + r0) * IN_DIM + j * 8;
    const size_t rows16 = (size_t)16 * IN_DIM;
    const uint32_t dA = sbase + (uint32_t)(r0 * 128) + swj;
    const uint32_t dB = dA + ASTAGE;

#define LOAD_STAGE(slot, kk) do {                                            \
        const uint32_t so = (uint32_t)(slot) * STAGE;                        \
        const int koff = (kk) * BK;                                          \
        _Pragma("unroll")                                                    \
        for (int i = 0; i < 8; i++)                                          \
            CP_ASYNC16(dA + so + (uint32_t)(i * 16 * 128),                   \
                       (const void*)(srcA + i * rows16 + koff));             \
        _Pragma("unroll")                                                    \
        for (int i = 0; i < 8; i++)                                          \
            CP_ASYNC16(dB + so + (uint32_t)(i * 16 * 128),                   \
                       (const void*)(srcB + i * rows16 + koff));             \
    } while (0)

    LOAD_STAGE(0, 0); CP_COMMIT();
    LOAD_STAGE(1, 1); CP_COMMIT();

    // ---- ldmatrix lane bases (row&7 == lane&7 everywhere -> fixed XOR) ----
    const uint32_t sw   = (uint32_t)(lane & 7);
    const uint32_t hi_a = (uint32_t)(lane >> 4);          // A k-chunk parity
    const uint32_t hi_b = (uint32_t)((lane >> 3) & 1);    // B k-chunk parity
    const uint32_t arow = (uint32_t)(m_w + ((lane >> 3) & 1) * 8 + (lane & 7));
    const uint32_t brow = (uint32_t)(n_w + (lane >> 4) * 8 + (lane & 7));
    const uint32_t aBase = arow * 128;            // + mi*2048 + chunk*16
    const uint32_t bBase = brow * 128 + ASTAGE;   // + p*2048  + chunk*16

    float acc[4][8][4];
#pragma unroll
    for (int i = 0; i < 4; i++)
#pragma unroll
        for (int nn = 0; nn < 8; nn++)
#pragma unroll
            for (int e = 0; e < 4; e++) acc[i][nn][e] = 0.0f;

    int cslot = 0;   // compute slot
    int lslot = 2;   // load slot
#pragma unroll 1
    for (int ki = 0; ki < KITERS; ki++) {
        CP_WAIT1();
        __syncthreads();
        if (ki + 2 < KITERS) LOAD_STAGE(lslot, ki + 2);
        CP_COMMIT();
        if (++lslot == NSTAGES) lslot = 0;

        const uint32_t st = sbase + (uint32_t)cslot * STAGE;
        if (++cslot == NSTAGES) cslot = 0;
#pragma unroll
        for (int s = 0; s < 4; s++) {                 // four k16 steps
            const uint32_t ca = ((uint32_t)(2 * s) + hi_a) ^ sw;
            const uint32_t cb = ((uint32_t)(2 * s) + hi_b) ^ sw;
            uint32_t afr[4][4];
#pragma unroll
            for (int mi = 0; mi < 4; mi++)
                ldsm_x4(afr[mi], st + aBase + (uint32_t)(mi * 2048) + ca * 16);
            uint32_t bfr[8][2];
#pragma unroll
            for (int p = 0; p < 4; p++) {
                uint32_t r[4];
                ldsm_x4(r, st + bBase + (uint32_t)(p * 2048) + cb * 16);
                bfr[2 * p][0] = r[0]; bfr[2 * p][1] = r[1];
                bfr[2 * p + 1][0] = r[2]; bfr[2 * p + 1][1] = r[3];
            }
#pragma unroll
            for (int mi = 0; mi < 4; mi++)
#pragma unroll
                for (int ni = 0; ni < 8; ni++)
                    mma16816(acc[mi][ni], afr[mi], bfr[ni]);
        }
    }

    // ---- epilogue: cosine scaling, float2 stores ----
    const int g = lane >> 2;
    const int q = lane & 3;
    float wn0[8], wn1[8];
#pragma unroll
    for (int ni = 0; ni < 8; ni++) {
        const int c = n0 + n_w + ni * 8 + q * 2;
        wn0[ni] = g_inv_wn[c];
        wn1[ni] = g_inv_wn[c + 1];
    }
#pragma unroll
    for (int mi = 0; mi < 4; mi++) {
        const int r = m0 + m_w + mi * 16 + g;
        const float sx0 = g_inv_xn[r];
        const float sx1 = g_inv_xn[r + 8];
#pragma unroll
        for (int ni = 0; ni < 8; ni++) {
            const int c = n0 + n_w + ni * 8 + q * 2;
            float2 v0 = make_float2(acc[mi][ni][0] * sx0 * wn0[ni],
                                    acc[mi][ni][1] * sx0 * wn1[ni]);
            float2 v1 = make_float2(acc[mi][ni][2] * sx1 * wn0[ni],
                                    acc[mi][ni][3] * sx1 * wn1[ni]);
            *(float2*)&out[(size_t)r * OUT_DIM + c] = v0;
            *(float2*)&out[(size_t)(r + 8) * OUT_DIM + c] = v1;
        }
    }
#undef LOAD_STAGE
}

// ---------------------------------------------------------------------------
// Launch
// ---------------------------------------------------------------------------
extern "C" void kernel_launch(void* const* d_in, const int* in_sizes, int n_in,
                              void* d_out, int out_size) {
    const float* x = (const float*)d_in[0];       // (4096, 4096)
    const float* w = (const float*)d_in[1];       // (4096, 32768)
    float* out = (float*)d_out;                   // (4096, 32768)

    cudaFuncSetAttribute(k_gemm, cudaFuncAttributeMaxDynamicSharedMemorySize,
                         SMEM_TOTAL);

    k_prep_x<<<BATCH, 256>>>(x);
    k_transpose_w<<<dim3(OUT_DIM / 32, IN_DIM / 32), 256>>>(w);
    k_wnorm<<<OUT_DIM / 8, 256>>>();
    k_gemm<<<(BATCH / BM) * (OUT_DIM / BN), 128, SMEM_TOTAL>>>(out);
}